// round 16
// baseline (speedup 1.0000x reference)
#include <cuda_runtime.h>
#include <math.h>

#define N_ 20000
#define E_ 320000
#define G_ 128
#define H_ 64
#define L_ 4
#define AVG_D_LOG 2.8332133440562162f  /* log(17.0) */

typedef unsigned long long ull;

/* ------------------------------------------------------------------ */
/* Scratch (zero-initialized at load; re-zeroed by k_rezero at the     */
/* END of every kernel_launch so each replay starts clean)             */
/* ------------------------------------------------------------------ */
__device__ int   g_degi[N_];
__device__ float g_amp[N_], g_att[N_];
__device__ int   g_rowoff[N_ + 1];
__device__ int   g_cursor[N_];
__device__ int   g_psrc[E_], g_pdst[E_];
__device__ float g_x[N_ * H_];
__device__ float g_m[E_ * H_];
__device__ float g_agg[N_ * 4 * H_];
__device__ float g_y[N_ * H_];
__device__ float g_gsum[G_ * H_];
__device__ float g_gcnt[G_];

/* ------------------------------------------------------------------ */
/* Packed f32x2 helpers                                                */
/* ------------------------------------------------------------------ */
__device__ __forceinline__ ull pk2(float x, float y)
{
    ull r;
    asm("mov.b64 %0, {%1,%2};" : "=l"(r) : "f"(x), "f"(y));
    return r;
}
__device__ __forceinline__ void fma2(ull& d, ull a, ull b)
{
    asm("fma.rn.f32x2 %0, %1, %2, %0;" : "+l"(d) : "l"(a), "l"(b));
}
__device__ __forceinline__ void upk2(ull v, float& x, float& y)
{
    asm("mov.b64 {%0,%1}, %2;" : "=f"(x), "=f"(y) : "l"(v));
}

/* ------------------------------------------------------------------ */
/* launch 1: degree count + graph-count (relies on pre-zeroed buffers) */
/* ------------------------------------------------------------------ */
__global__ void k_count_gcnt(const int* __restrict__ dst,
                             const int* __restrict__ gid)
{
    int i = blockIdx.x * blockDim.x + threadIdx.x;
    if (i < E_) atomicAdd(&g_degi[dst[i]], 1);
    if (i < N_) atomicAdd(&g_gcnt[gid[i]], 1.0f);
}

/* ------------------------------------------------------------------ */
/* launch 2: block scan -> rowoff + cursor                             */
/* ------------------------------------------------------------------ */
__global__ void k_scan()
{
    int t  = threadIdx.x;
    int i0 = t * 20;
    int loc[20];
    int s = 0;
#pragma unroll
    for (int k = 0; k < 20; k++) {
        int i = i0 + k;
        int v = (i < N_) ? g_degi[i] : 0;
        loc[k] = s;
        s += v;
    }
    int lane = t & 31, w = t >> 5;
    int x = s;
#pragma unroll
    for (int off = 1; off < 32; off <<= 1) {
        int y = __shfl_up_sync(0xffffffffu, x, off);
        if (lane >= off) x += y;
    }
    __shared__ int wsum[32];
    if (lane == 31) wsum[w] = x;
    __syncthreads();
    if (w == 0) {
        int y = wsum[lane];
#pragma unroll
        for (int off = 1; off < 32; off <<= 1) {
            int z = __shfl_up_sync(0xffffffffu, y, off);
            if (lane >= off) y += z;
        }
        wsum[lane] = y;
    }
    __syncthreads();
    int base = x - s + ((w > 0) ? wsum[w - 1] : 0);
#pragma unroll
    for (int k = 0; k < 20; k++) {
        int i = i0 + k;
        if (i <= N_) {
            int off = base + loc[k];
            g_rowoff[i] = off;
            if (i < N_) g_cursor[i] = off;
        }
    }
}

/* ------------------------------------------------------------------ */
/* launch 3: scatter + degree scalers + embedding, one grid            */
/* ------------------------------------------------------------------ */
__global__ void k_scatter_scalers_embed(const int* __restrict__ src,
                                        const int* __restrict__ dst,
                                        const float* __restrict__ h,
                                        const float* __restrict__ embW,
                                        const float* __restrict__ embB)
{
    int id = blockIdx.x * blockDim.x + threadIdx.x;
    if (id < E_) {
        int d = dst[id];
        int p = atomicAdd(&g_cursor[d], 1);
        g_psrc[p] = src[id];
        g_pdst[p] = d;
    }
    if (id < N_) {
        float d    = (float)g_degi[id];
        float logd = logf(d + 1.0f);
        g_amp[id] = logd / AVG_D_LOG;
        g_att[id] = AVG_D_LOG / fmaxf(logd, 1e-5f);
    }
    if (id < N_ * H_) {
        int n = id >> 6, c = id & 63;
        const float* hr = h + n * 16;
        float a = embB[c];
#pragma unroll
        for (int k = 0; k < 16; k++)
            a = fmaf(hr[k], embW[k * H_ + c], a);
        g_x[id] = a;
    }
}

/* ------------------------------------------------------------------ */
/* launch 4 (= ncu slot): edge pretrans GEMM (R13 version, frozen).    */
/* ------------------------------------------------------------------ */
__global__ void __launch_bounds__(256, 4)
k_edge(const float* __restrict__ preW, const float* __restrict__ preB)
{
    __shared__ float sA[64][68];   /* [edge][k], 272B row = 16B aligned */
    __shared__ float sB[64][68];   /* [k][col]                          */

    int t  = threadIdx.x;
    int e0 = blockIdx.x * 64;
    int tx = t & 15, ty = t >> 4;

    ull acc[4][2];
#pragma unroll
    for (int i = 0; i < 4; i++) { acc[i][0] = pk2(0.f, 0.f); acc[i][1] = pk2(0.f, 0.f); }

    for (int kt = 0; kt < 2; kt++) {
        /* B tile: preW rows kt*64 .. kt*64+63 */
#pragma unroll
        for (int r = 0; r < 4; r++) {
            int li  = t + 256 * r;          /* float4 index 0..1023 */
            int row = li >> 4, c4 = li & 15;
            float4 wv = *(const float4*)(preW + (kt * 64 + row) * 64 + c4 * 4);
            *(float4*)&sB[row][c4 * 4] = wv;
        }
        /* A tile gather: row e = x[src[p]] (kt=0) or x[dst[p]] (kt=1) */
#pragma unroll
        for (int r = 0; r < 4; r++) {
            int li = t + 256 * r;
            int e = li >> 4, c4 = li & 15;
            int p = e0 + e;
            float4 v = make_float4(0.f, 0.f, 0.f, 0.f);
            if (p < E_) {
                int nd = (kt == 0) ? g_psrc[p] : g_pdst[p];
                v = *(const float4*)(g_x + nd * 64 + c4 * 4);
            }
            *(float4*)&sA[e][c4 * 4] = v;
        }
        __syncthreads();

        /* inner loop: 4 kk per step, all-LDS.128 */
#pragma unroll 4
        for (int k4 = 0; k4 < 16; k4++) {
            float4 a0 = *(const float4*)&sA[ty * 4 + 0][k4 * 4];
            float4 a1 = *(const float4*)&sA[ty * 4 + 1][k4 * 4];
            float4 a2 = *(const float4*)&sA[ty * 4 + 2][k4 * 4];
            float4 a3 = *(const float4*)&sA[ty * 4 + 3][k4 * 4];
            float4 b0 = *(const float4*)&sB[k4 * 4 + 0][tx * 4];
            float4 b1 = *(const float4*)&sB[k4 * 4 + 1][tx * 4];
            float4 b2 = *(const float4*)&sB[k4 * 4 + 2][tx * 4];
            float4 b3 = *(const float4*)&sB[k4 * 4 + 3][tx * 4];

            {
                ull B01 = pk2(b0.x, b0.y), B23 = pk2(b0.z, b0.w);
                ull A;
                A = pk2(a0.x, a0.x); fma2(acc[0][0], A, B01); fma2(acc[0][1], A, B23);
                A = pk2(a1.x, a1.x); fma2(acc[1][0], A, B01); fma2(acc[1][1], A, B23);
                A = pk2(a2.x, a2.x); fma2(acc[2][0], A, B01); fma2(acc[2][1], A, B23);
                A = pk2(a3.x, a3.x); fma2(acc[3][0], A, B01); fma2(acc[3][1], A, B23);
            }
            {
                ull B01 = pk2(b1.x, b1.y), B23 = pk2(b1.z, b1.w);
                ull A;
                A = pk2(a0.y, a0.y); fma2(acc[0][0], A, B01); fma2(acc[0][1], A, B23);
                A = pk2(a1.y, a1.y); fma2(acc[1][0], A, B01); fma2(acc[1][1], A, B23);
                A = pk2(a2.y, a2.y); fma2(acc[2][0], A, B01); fma2(acc[2][1], A, B23);
                A = pk2(a3.y, a3.y); fma2(acc[3][0], A, B01); fma2(acc[3][1], A, B23);
            }
            {
                ull B01 = pk2(b2.x, b2.y), B23 = pk2(b2.z, b2.w);
                ull A;
                A = pk2(a0.z, a0.z); fma2(acc[0][0], A, B01); fma2(acc[0][1], A, B23);
                A = pk2(a1.z, a1.z); fma2(acc[1][0], A, B01); fma2(acc[1][1], A, B23);
                A = pk2(a2.z, a2.z); fma2(acc[2][0], A, B01); fma2(acc[2][1], A, B23);
                A = pk2(a3.z, a3.z); fma2(acc[3][0], A, B01); fma2(acc[3][1], A, B23);
            }
            {
                ull B01 = pk2(b3.x, b3.y), B23 = pk2(b3.z, b3.w);
                ull A;
                A = pk2(a0.w, a0.w); fma2(acc[0][0], A, B01); fma2(acc[0][1], A, B23);
                A = pk2(a1.w, a1.w); fma2(acc[1][0], A, B01); fma2(acc[1][1], A, B23);
                A = pk2(a2.w, a2.w); fma2(acc[2][0], A, B01); fma2(acc[2][1], A, B23);
                A = pk2(a3.w, a3.w); fma2(acc[3][0], A, B01); fma2(acc[3][1], A, B23);
            }
        }
        __syncthreads();
    }

    float4 bias = *(const float4*)&preB[tx * 4];
#pragma unroll
    for (int i = 0; i < 4; i++) {
        int p = e0 + ty * 4 + i;
        if (p >= E_) continue;
        float x0, x1, x2, x3;
        upk2(acc[i][0], x0, x1);
        upk2(acc[i][1], x2, x3);
        float4 o = make_float4(x0 + bias.x, x1 + bias.y, x2 + bias.z, x3 + bias.w);
        *(float4*)(g_m + (size_t)p * 64 + tx * 4) = o;
    }
}

/* ------------------------------------------------------------------ */
/* Aggregate: warp per node, CSR walk, 4-wide unrolled for MLP         */
/* ------------------------------------------------------------------ */
__global__ void k_agg()
{
    int gw   = (blockIdx.x * blockDim.x + threadIdx.x) >> 5;
    int lane = threadIdx.x & 31;
    if (gw >= N_) return;

    int r0 = g_rowoff[gw], r1 = g_rowoff[gw + 1];
    float sx = 0.f, sy = 0.f, qx = 0.f, qy = 0.f;
    float mxx = -INFINITY, mxy = -INFINITY;
    float mnx =  INFINITY, mny =  INFINITY;

    const float2* M = (const float2*)g_m;
    int p = r0;
    for (; p + 4 <= r1; p += 4) {
        float2 v0 = M[(p + 0) * 32 + lane];
        float2 v1 = M[(p + 1) * 32 + lane];
        float2 v2 = M[(p + 2) * 32 + lane];
        float2 v3 = M[(p + 3) * 32 + lane];
        sx += v0.x; sy += v0.y;
        qx = fmaf(v0.x, v0.x, qx); qy = fmaf(v0.y, v0.y, qy);
        mxx = fmaxf(mxx, v0.x); mxy = fmaxf(mxy, v0.y);
        mnx = fminf(mnx, v0.x); mny = fminf(mny, v0.y);
        sx += v1.x; sy += v1.y;
        qx = fmaf(v1.x, v1.x, qx); qy = fmaf(v1.y, v1.y, qy);
        mxx = fmaxf(mxx, v1.x); mxy = fmaxf(mxy, v1.y);
        mnx = fminf(mnx, v1.x); mny = fminf(mny, v1.y);
        sx += v2.x; sy += v2.y;
        qx = fmaf(v2.x, v2.x, qx); qy = fmaf(v2.y, v2.y, qy);
        mxx = fmaxf(mxx, v2.x); mxy = fmaxf(mxy, v2.y);
        mnx = fminf(mnx, v2.x); mny = fminf(mny, v2.y);
        sx += v3.x; sy += v3.y;
        qx = fmaf(v3.x, v3.x, qx); qy = fmaf(v3.y, v3.y, qy);
        mxx = fmaxf(mxx, v3.x); mxy = fmaxf(mxy, v3.y);
        mnx = fminf(mnx, v3.x); mny = fminf(mny, v3.y);
    }
    for (; p < r1; p++) {
        float2 v = M[p * 32 + lane];
        sx += v.x; sy += v.y;
        qx = fmaf(v.x, v.x, qx); qy = fmaf(v.y, v.y, qy);
        mxx = fmaxf(mxx, v.x); mxy = fmaxf(mxy, v.y);
        mnx = fminf(mnx, v.x); mny = fminf(mny, v.y);
    }
    int   deg  = r1 - r0;
    float degc = fmaxf((float)deg, 1.0f);
    float meanx = sx / degc, meany = sy / degc;
    float msqx  = qx / degc, msqy  = qy / degc;
    float stdx = sqrtf(fmaxf(msqx - meanx * meanx, 0.f) + 1e-5f);
    float stdy = sqrtf(fmaxf(msqy - meany * meany, 0.f) + 1e-5f);
    if (deg == 0) { mxx = mxy = 0.f; mnx = mny = 0.f; }

    float2* A = (float2*)(g_agg + gw * (4 * H_));
    A[lane]      = make_float2(meanx, meany);
    A[32 + lane] = make_float2(mxx, mxy);
    A[64 + lane] = make_float2(mnx, mny);
    A[96 + lane] = make_float2(stdx, stdy);
}

/* ------------------------------------------------------------------ */
/* Posttrans GEMM, 3-accumulator, BM=32 (625 blocks for latency cover) */
/*   y = agg@W0 + amp*(agg@W1) + att*(agg@W2) + x@W3 + bias            */
/* ------------------------------------------------------------------ */
__global__ void __launch_bounds__(256)
k_post(const float* __restrict__ postW, const float* __restrict__ postB)
{
    __shared__ float sA[32][33];
    __shared__ float sB0[32][68];
    __shared__ float sB1[32][68];
    __shared__ float sB2[32][68];
    __shared__ float sAmp[32], sAtt[32];

    int t  = threadIdx.x;
    int n0 = blockIdx.x * 32;
    if (t < 32) {
        int n = n0 + t;
        sAmp[t] = (n < N_) ? g_amp[n] : 0.f;
        sAtt[t] = (n < N_) ? g_att[n] : 0.f;
    }
    __syncthreads();

    int tx = t & 15, ty = t >> 4;     /* tx: 4 cols, ty: 2 nodes */
    ull acc0[2][2], acc1[2][2], acc2[2][2];
#pragma unroll
    for (int i = 0; i < 2; i++) {
        acc0[i][0] = 0ull; acc0[i][1] = 0ull;
        acc1[i][0] = 0ull; acc1[i][1] = 0ull;
        acc2[i][0] = 0ull; acc2[i][1] = 0ull;
    }

    /* main: 8 phases over agg K=256, three weight tiles per phase */
    for (int kt = 0; kt < 8; kt++) {
#pragma unroll
        for (int r = 0; r < 2; r++) {
            int li = t + 256 * r;           /* float4 index 0..511 */
            int kl = li >> 4, c4 = li & 15;
            int row = kt * 32 + kl;
            *(float4*)&sB0[kl][c4 * 4] = *(const float4*)(postW + row * 64 + c4 * 4);
            *(float4*)&sB1[kl][c4 * 4] = *(const float4*)(postW + (256 + row) * 64 + c4 * 4);
            *(float4*)&sB2[kl][c4 * 4] = *(const float4*)(postW + (512 + row) * 64 + c4 * 4);
        }
#pragma unroll
        for (int r = 0; r < 4; r++) {
            int li = t + 256 * r;           /* 0..1023 */
            int nl = li >> 5, kl = li & 31;
            int n  = n0 + nl;
            sA[kl][nl] = (n < N_) ? g_agg[n * 256 + kt * 32 + kl] : 0.f;
        }
        __syncthreads();
#pragma unroll 4
        for (int kk = 0; kk < 32; kk++) {
            float a0 = sA[kk][ty * 2 + 0];
            float a1 = sA[kk][ty * 2 + 1];
            ull A0 = pk2(a0, a0), A1 = pk2(a1, a1);
            {
                float4 b = *(const float4*)&sB0[kk][tx * 4];
                ull B01 = pk2(b.x, b.y), B23 = pk2(b.z, b.w);
                fma2(acc0[0][0], A0, B01); fma2(acc0[0][1], A0, B23);
                fma2(acc0[1][0], A1, B01); fma2(acc0[1][1], A1, B23);
            }
            {
                float4 b = *(const float4*)&sB1[kk][tx * 4];
                ull B01 = pk2(b.x, b.y), B23 = pk2(b.z, b.w);
                fma2(acc1[0][0], A0, B01); fma2(acc1[0][1], A0, B23);
                fma2(acc1[1][0], A1, B01); fma2(acc1[1][1], A1, B23);
            }
            {
                float4 b = *(const float4*)&sB2[kk][tx * 4];
                ull B01 = pk2(b.x, b.y), B23 = pk2(b.z, b.w);
                fma2(acc2[0][0], A0, B01); fma2(acc2[0][1], A0, B23);
                fma2(acc2[1][0], A1, B01); fma2(acc2[1][1], A1, B23);
            }
        }
        __syncthreads();
    }

    /* tail: x @ W3 (rows 768..831) accumulated into acc0 */
    for (int kt2 = 0; kt2 < 2; kt2++) {
#pragma unroll
        for (int r = 0; r < 2; r++) {
            int li = t + 256 * r;
            int kl = li >> 4, c4 = li & 15;
            int row = 768 + kt2 * 32 + kl;
            *(float4*)&sB0[kl][c4 * 4] = *(const float4*)(postW + row * 64 + c4 * 4);
        }
#pragma unroll
        for (int r = 0; r < 4; r++) {
            int li = t + 256 * r;
            int nl = li >> 5, kl = li & 31;
            int n  = n0 + nl;
            sA[kl][nl] = (n < N_) ? g_x[n * 64 + kt2 * 32 + kl] : 0.f;
        }
        __syncthreads();
#pragma unroll 8
        for (int kk = 0; kk < 32; kk++) {
            float4 b = *(const float4*)&sB0[kk][tx * 4];
            ull B01 = pk2(b.x, b.y), B23 = pk2(b.z, b.w);
#pragma unroll
            for (int i = 0; i < 2; i++) {
                float a = sA[kk][ty * 2 + i];
                ull A = pk2(a, a);
                fma2(acc0[i][0], A, B01);
                fma2(acc0[i][1], A, B23);
            }
        }
        __syncthreads();
    }

    /* epilogue: y = acc0 + amp*acc1 + att*acc2 + bias */
#pragma unroll
    for (int i = 0; i < 2; i++) {
        int n = n0 + ty * 2 + i;
        if (n >= N_) continue;
        float amp = sAmp[ty * 2 + i];
        float att = sAtt[ty * 2 + i];
        float y[4], u1[4], u2[4];
        upk2(acc0[i][0], y[0], y[1]);
        upk2(acc0[i][1], y[2], y[3]);
        upk2(acc1[i][0], u1[0], u1[1]);
        upk2(acc1[i][1], u1[2], u1[3]);
        upk2(acc2[i][0], u2[0], u2[1]);
        upk2(acc2[i][1], u2[2], u2[3]);
        int c = tx * 4;
#pragma unroll
        for (int j = 0; j < 4; j++) {
            float v = y[j] + amp * u1[j] + att * u2[j] + postB[c + j];
            g_y[n * 64 + c + j] = v;
        }
    }
}

/* ------------------------------------------------------------------ */
/* Mix (R14 version)                                                   */
/* ------------------------------------------------------------------ */
__global__ void __launch_bounds__(256, 4)
k_mix(const float* __restrict__ mixW,
      const float* __restrict__ mixB,
      const float* __restrict__ snorm)
{
    __shared__ float sY[64][68];   /* [node][k], natural layout */
    __shared__ float sW[64][68];   /* [k][col]                  */

    int t  = threadIdx.x;
    int n0 = blockIdx.x * 64;
    int tx = t & 15, ty = t >> 4;

#pragma unroll
    for (int r = 0; r < 4; r++) {
        int li  = t + 256 * r;
        int row = li >> 4, c4 = li & 15;
        int n = n0 + row;
        float4 yv = make_float4(0.f, 0.f, 0.f, 0.f);
        if (n < N_) yv = *(const float4*)(g_y + n * 64 + c4 * 4);
        *(float4*)&sY[row][c4 * 4] = yv;
        *(float4*)&sW[row][c4 * 4] = *(const float4*)(mixW + row * 64 + c4 * 4);
    }
    __syncthreads();

    ull acc[4][2];
#pragma unroll
    for (int i = 0; i < 4; i++) { acc[i][0] = pk2(0.f, 0.f); acc[i][1] = pk2(0.f, 0.f); }

#pragma unroll 4
    for (int k4 = 0; k4 < 16; k4++) {
        float4 a0 = *(const float4*)&sY[ty * 4 + 0][k4 * 4];
        float4 a1 = *(const float4*)&sY[ty * 4 + 1][k4 * 4];
        float4 a2 = *(const float4*)&sY[ty * 4 + 2][k4 * 4];
        float4 a3 = *(const float4*)&sY[ty * 4 + 3][k4 * 4];
        float4 b0 = *(const float4*)&sW[k4 * 4 + 0][tx * 4];
        float4 b1 = *(const float4*)&sW[k4 * 4 + 1][tx * 4];
        float4 b2 = *(const float4*)&sW[k4 * 4 + 2][tx * 4];
        float4 b3 = *(const float4*)&sW[k4 * 4 + 3][tx * 4];

        {
            ull B01 = pk2(b0.x, b0.y), B23 = pk2(b0.z, b0.w);
            ull A;
            A = pk2(a0.x, a0.x); fma2(acc[0][0], A, B01); fma2(acc[0][1], A, B23);
            A = pk2(a1.x, a1.x); fma2(acc[1][0], A, B01); fma2(acc[1][1], A, B23);
            A = pk2(a2.x, a2.x); fma2(acc[2][0], A, B01); fma2(acc[2][1], A, B23);
            A = pk2(a3.x, a3.x); fma2(acc[3][0], A, B01); fma2(acc[3][1], A, B23);
        }
        {
            ull B01 = pk2(b1.x, b1.y), B23 = pk2(b1.z, b1.w);
            ull A;
            A = pk2(a0.y, a0.y); fma2(acc[0][0], A, B01); fma2(acc[0][1], A, B23);
            A = pk2(a1.y, a1.y); fma2(acc[1][0], A, B01); fma2(acc[1][1], A, B23);
            A = pk2(a2.y, a2.y); fma2(acc[2][0], A, B01); fma2(acc[2][1], A, B23);
            A = pk2(a3.y, a3.y); fma2(acc[3][0], A, B01); fma2(acc[3][1], A, B23);
        }
        {
            ull B01 = pk2(b2.x, b2.y), B23 = pk2(b2.z, b2.w);
            ull A;
            A = pk2(a0.z, a0.z); fma2(acc[0][0], A, B01); fma2(acc[0][1], A, B23);
            A = pk2(a1.z, a1.z); fma2(acc[1][0], A, B01); fma2(acc[1][1], A, B23);
            A = pk2(a2.z, a2.z); fma2(acc[2][0], A, B01); fma2(acc[2][1], A, B23);
            A = pk2(a3.z, a3.z); fma2(acc[3][0], A, B01); fma2(acc[3][1], A, B23);
        }
        {
            ull B01 = pk2(b3.x, b3.y), B23 = pk2(b3.z, b3.w);
            ull A;
            A = pk2(a0.w, a0.w); fma2(acc[0][0], A, B01); fma2(acc[0][1], A, B23);
            A = pk2(a1.w, a1.w); fma2(acc[1][0], A, B01); fma2(acc[1][1], A, B23);
            A = pk2(a2.w, a2.w); fma2(acc[2][0], A, B01); fma2(acc[2][1], A, B23);
            A = pk2(a3.w, a3.w); fma2(acc[3][0], A, B01); fma2(acc[3][1], A, B23);
        }
    }

#pragma unroll
    for (int i = 0; i < 4; i++) {
        int n = n0 + ty * 4 + i;
        if (n >= N_) continue;
        float sn = snorm[n];
        float v[4];
        upk2(acc[i][0], v[0], v[1]);
        upk2(acc[i][1], v[2], v[3]);
        float* xp = g_x + n * 64 + tx * 4;
        float4 cur = *(float4*)xp;
        float u0 = v[0] + mixB[tx * 4 + 0]; u0 = (u0 > 0.f) ? u0 : 0.01f * u0;
        float u1 = v[1] + mixB[tx * 4 + 1]; u1 = (u1 > 0.f) ? u1 : 0.01f * u1;
        float u2 = v[2] + mixB[tx * 4 + 2]; u2 = (u2 > 0.f) ? u2 : 0.01f * u2;
        float u3 = v[3] + mixB[tx * 4 + 3]; u3 = (u3 > 0.f) ? u3 : 0.01f * u3;
        cur.x += u0 * sn; cur.y += u1 * sn;
        cur.z += u2 * sn; cur.w += u3 * sn;
        *(float4*)xp = cur;
    }
}

/* ------------------------------------------------------------------ */
/* Readout                                                             */
/* ------------------------------------------------------------------ */
__global__ void k_gaccum(const int* __restrict__ gid)
{
    int id = blockIdx.x * blockDim.x + threadIdx.x;
    if (id >= N_ * H_) return;
    int n = id >> 6, c = id & 63;
    atomicAdd(&g_gsum[gid[n] * 64 + c], g_x[id]);
}

__global__ void k_final(const float* __restrict__ r1W, const float* __restrict__ r1B,
                        const float* __restrict__ r2W, const float* __restrict__ r2B,
                        const float* __restrict__ r3W, const float* __restrict__ r3B,
                        float* __restrict__ out)
{
    int g = threadIdx.x;
    if (g >= G_) return;
    float cnt = fmaxf(g_gcnt[g], 1.0f);
    float hg[64];
#pragma unroll
    for (int k = 0; k < 64; k++) hg[k] = g_gsum[g * 64 + k] / cnt;

    float t1[32];
#pragma unroll
    for (int j = 0; j < 32; j++) {
        float a = r1B[j];
        for (int k = 0; k < 64; k++) a = fmaf(hg[k], r1W[k * 32 + j], a);
        t1[j] = fmaxf(a, 0.f);
    }
    float t2[16];
#pragma unroll
    for (int j = 0; j < 16; j++) {
        float a = r2B[j];
        for (int k = 0; k < 32; k++) a = fmaf(t1[k], r2W[k * 16 + j], a);
        t2[j] = fmaxf(a, 0.f);
    }
#pragma unroll
    for (int c = 0; c < 10; c++) {
        float a = r3B[c];
        for (int k = 0; k < 16; k++) a = fmaf(t2[k], r3W[k * 10 + c], a);
        out[g * 10 + c] = a;
    }
}

/* trailing re-zero so the next replay starts from clean counters      */
__global__ void k_rezero()
{
    int i = blockIdx.x * blockDim.x + threadIdx.x;
    if (i < N_)       g_degi[i] = 0;
    if (i < G_)       g_gcnt[i] = 0.f;
    if (i < G_ * H_)  g_gsum[i] = 0.f;
}

/* ------------------------------------------------------------------ */
/* Host launch                                                         */
/* ------------------------------------------------------------------ */
extern "C" void kernel_launch(void* const* d_in, const int* in_sizes, int n_in,
                              void* d_out, int out_size)
{
    const float* h      = (const float*)d_in[0];
    const float* snorm  = (const float*)d_in[1];
    const float* embW   = (const float*)d_in[2];
    const float* embB   = (const float*)d_in[3];
    const float* preW   = (const float*)d_in[4];
    const float* preB   = (const float*)d_in[5];
    const float* postW  = (const float*)d_in[6];
    const float* postB  = (const float*)d_in[7];
    const float* mixW   = (const float*)d_in[8];
    const float* mixB   = (const float*)d_in[9];
    const float* r1W    = (const float*)d_in[10];
    const float* r1B    = (const float*)d_in[11];
    const float* r2W    = (const float*)d_in[12];
    const float* r2B    = (const float*)d_in[13];
    const float* r3W    = (const float*)d_in[14];
    const float* r3B    = (const float*)d_in[15];
    const int*   src    = (const int*)d_in[16];
    const int*   dst    = (const int*)d_in[17];
    const int*   gid    = (const int*)d_in[18];
    float* out = (float*)d_out;

    /* 3 prelude launches; k_edge layer-0 is launch #4 = ncu slot */
    k_count_gcnt          <<<(E_ + 255) / 256, 256>>>(dst, gid);
    k_scan                <<<1, 1024>>>();
    k_scatter_scalers_embed<<<(N_ * H_ + 255) / 256, 256>>>(src, dst, h, embW, embB);

    for (int i = 0; i < L_; i++) {
        k_edge<<<(E_ + 63) / 64, 256>>>(preW + i * 128 * 64, preB + i * 64);
        k_agg <<<(N_ * 32 + 255) / 256, 256>>>();
        k_post<<<(N_ + 31) / 32, 256>>>(postW + i * 832 * 64, postB + i * 64);
        k_mix <<<(N_ + 63) / 64, 256>>>(mixW + i * 64 * 64, mixB + i * 64, snorm);
    }

    k_gaccum<<<(N_ * H_ + 255) / 256, 256>>>(gid);
    k_final <<<1, 128>>>(r1W, r1B, r2W, r2B, r3W, r3B, out);
    k_rezero<<<(N_ + 255) / 256, 256>>>();
}

// round 17
// speedup vs baseline: 1.7113x; 1.7113x over previous
#include <cuda_runtime.h>
#include <math.h>

#define N_ 20000
#define E_ 320000
#define G_ 128
#define H_ 64
#define L_ 4
#define AVG_D_LOG 2.8332133440562162f  /* log(17.0) */

typedef unsigned long long ull;

/* ------------------------------------------------------------------ */
/* Scratch (zero-initialized at load; re-zeroed by k_rezero at the     */
/* END of every kernel_launch so each replay starts clean)             */
/* ------------------------------------------------------------------ */
__device__ int   g_degi[N_];
__device__ float g_amp[N_], g_att[N_];
__device__ int   g_rowoff[N_ + 1];
__device__ int   g_cursor[N_];
__device__ int   g_psrc[E_], g_pdst[E_];
__device__ float g_x[N_ * H_];
__device__ float g_m[E_ * H_];
__device__ float g_agg[N_ * 4 * H_];
__device__ float g_y[N_ * H_];
__device__ float g_gsum[G_ * H_];
__device__ float g_gcnt[G_];

/* ------------------------------------------------------------------ */
/* Packed f32x2 helpers                                                */
/* ------------------------------------------------------------------ */
__device__ __forceinline__ ull pk2(float x, float y)
{
    ull r;
    asm("mov.b64 %0, {%1,%2};" : "=l"(r) : "f"(x), "f"(y));
    return r;
}
__device__ __forceinline__ void fma2(ull& d, ull a, ull b)
{
    asm("fma.rn.f32x2 %0, %1, %2, %0;" : "+l"(d) : "l"(a), "l"(b));
}
__device__ __forceinline__ void upk2(ull v, float& x, float& y)
{
    asm("mov.b64 {%0,%1}, %2;" : "=f"(x), "=f"(y) : "l"(v));
}

/* ------------------------------------------------------------------ */
/* launch 1: degree count + graph-count (relies on pre-zeroed buffers) */
/* ------------------------------------------------------------------ */
__global__ void k_count_gcnt(const int* __restrict__ dst,
                             const int* __restrict__ gid)
{
    int i = blockIdx.x * blockDim.x + threadIdx.x;
    if (i < E_) atomicAdd(&g_degi[dst[i]], 1);
    if (i < N_) atomicAdd(&g_gcnt[gid[i]], 1.0f);
}

/* ------------------------------------------------------------------ */
/* launch 2: block scan -> rowoff + cursor                             */
/* ------------------------------------------------------------------ */
__global__ void k_scan()
{
    int t  = threadIdx.x;
    int i0 = t * 20;
    int loc[20];
    int s = 0;
#pragma unroll
    for (int k = 0; k < 20; k++) {
        int i = i0 + k;
        int v = (i < N_) ? g_degi[i] : 0;
        loc[k] = s;
        s += v;
    }
    int lane = t & 31, w = t >> 5;
    int x = s;
#pragma unroll
    for (int off = 1; off < 32; off <<= 1) {
        int y = __shfl_up_sync(0xffffffffu, x, off);
        if (lane >= off) x += y;
    }
    __shared__ int wsum[32];
    if (lane == 31) wsum[w] = x;
    __syncthreads();
    if (w == 0) {
        int y = wsum[lane];
#pragma unroll
        for (int off = 1; off < 32; off <<= 1) {
            int z = __shfl_up_sync(0xffffffffu, y, off);
            if (lane >= off) y += z;
        }
        wsum[lane] = y;
    }
    __syncthreads();
    int base = x - s + ((w > 0) ? wsum[w - 1] : 0);
#pragma unroll
    for (int k = 0; k < 20; k++) {
        int i = i0 + k;
        if (i <= N_) {
            int off = base + loc[k];
            g_rowoff[i] = off;
            if (i < N_) g_cursor[i] = off;
        }
    }
}

/* ------------------------------------------------------------------ */
/* launch 3: scatter + degree scalers + embedding, one grid            */
/* ------------------------------------------------------------------ */
__global__ void k_scatter_scalers_embed(const int* __restrict__ src,
                                        const int* __restrict__ dst,
                                        const float* __restrict__ h,
                                        const float* __restrict__ embW,
                                        const float* __restrict__ embB)
{
    int id = blockIdx.x * blockDim.x + threadIdx.x;
    if (id < E_) {
        int d = dst[id];
        int p = atomicAdd(&g_cursor[d], 1);
        g_psrc[p] = src[id];
        g_pdst[p] = d;
    }
    if (id < N_) {
        float d    = (float)g_degi[id];
        float logd = logf(d + 1.0f);
        g_amp[id] = logd / AVG_D_LOG;
        g_att[id] = AVG_D_LOG / fmaxf(logd, 1e-5f);
    }
    if (id < N_ * H_) {
        int n = id >> 6, c = id & 63;
        const float* hr = h + n * 16;
        float a = embB[c];
#pragma unroll
        for (int k = 0; k < 16; k++)
            a = fmaf(hr[k], embW[k * H_ + c], a);
        g_x[id] = a;
    }
}

/* ------------------------------------------------------------------ */
/* launch 4 (= ncu slot): edge pretrans GEMM (R13 version, frozen).    */
/* ------------------------------------------------------------------ */
__global__ void __launch_bounds__(256, 4)
k_edge(const float* __restrict__ preW, const float* __restrict__ preB)
{
    __shared__ float sA[64][68];   /* [edge][k], 272B row = 16B aligned */
    __shared__ float sB[64][68];   /* [k][col]                          */

    int t  = threadIdx.x;
    int e0 = blockIdx.x * 64;
    int tx = t & 15, ty = t >> 4;

    ull acc[4][2];
#pragma unroll
    for (int i = 0; i < 4; i++) { acc[i][0] = pk2(0.f, 0.f); acc[i][1] = pk2(0.f, 0.f); }

    for (int kt = 0; kt < 2; kt++) {
        /* B tile: preW rows kt*64 .. kt*64+63 */
#pragma unroll
        for (int r = 0; r < 4; r++) {
            int li  = t + 256 * r;          /* float4 index 0..1023 */
            int row = li >> 4, c4 = li & 15;
            float4 wv = *(const float4*)(preW + (kt * 64 + row) * 64 + c4 * 4);
            *(float4*)&sB[row][c4 * 4] = wv;
        }
        /* A tile gather: row e = x[src[p]] (kt=0) or x[dst[p]] (kt=1) */
#pragma unroll
        for (int r = 0; r < 4; r++) {
            int li = t + 256 * r;
            int e = li >> 4, c4 = li & 15;
            int p = e0 + e;
            float4 v = make_float4(0.f, 0.f, 0.f, 0.f);
            if (p < E_) {
                int nd = (kt == 0) ? g_psrc[p] : g_pdst[p];
                v = *(const float4*)(g_x + nd * 64 + c4 * 4);
            }
            *(float4*)&sA[e][c4 * 4] = v;
        }
        __syncthreads();

        /* inner loop: 4 kk per step, all-LDS.128 */
#pragma unroll 4
        for (int k4 = 0; k4 < 16; k4++) {
            float4 a0 = *(const float4*)&sA[ty * 4 + 0][k4 * 4];
            float4 a1 = *(const float4*)&sA[ty * 4 + 1][k4 * 4];
            float4 a2 = *(const float4*)&sA[ty * 4 + 2][k4 * 4];
            float4 a3 = *(const float4*)&sA[ty * 4 + 3][k4 * 4];
            float4 b0 = *(const float4*)&sB[k4 * 4 + 0][tx * 4];
            float4 b1 = *(const float4*)&sB[k4 * 4 + 1][tx * 4];
            float4 b2 = *(const float4*)&sB[k4 * 4 + 2][tx * 4];
            float4 b3 = *(const float4*)&sB[k4 * 4 + 3][tx * 4];

            {
                ull B01 = pk2(b0.x, b0.y), B23 = pk2(b0.z, b0.w);
                ull A;
                A = pk2(a0.x, a0.x); fma2(acc[0][0], A, B01); fma2(acc[0][1], A, B23);
                A = pk2(a1.x, a1.x); fma2(acc[1][0], A, B01); fma2(acc[1][1], A, B23);
                A = pk2(a2.x, a2.x); fma2(acc[2][0], A, B01); fma2(acc[2][1], A, B23);
                A = pk2(a3.x, a3.x); fma2(acc[3][0], A, B01); fma2(acc[3][1], A, B23);
            }
            {
                ull B01 = pk2(b1.x, b1.y), B23 = pk2(b1.z, b1.w);
                ull A;
                A = pk2(a0.y, a0.y); fma2(acc[0][0], A, B01); fma2(acc[0][1], A, B23);
                A = pk2(a1.y, a1.y); fma2(acc[1][0], A, B01); fma2(acc[1][1], A, B23);
                A = pk2(a2.y, a2.y); fma2(acc[2][0], A, B01); fma2(acc[2][1], A, B23);
                A = pk2(a3.y, a3.y); fma2(acc[3][0], A, B01); fma2(acc[3][1], A, B23);
            }
            {
                ull B01 = pk2(b2.x, b2.y), B23 = pk2(b2.z, b2.w);
                ull A;
                A = pk2(a0.z, a0.z); fma2(acc[0][0], A, B01); fma2(acc[0][1], A, B23);
                A = pk2(a1.z, a1.z); fma2(acc[1][0], A, B01); fma2(acc[1][1], A, B23);
                A = pk2(a2.z, a2.z); fma2(acc[2][0], A, B01); fma2(acc[2][1], A, B23);
                A = pk2(a3.z, a3.z); fma2(acc[3][0], A, B01); fma2(acc[3][1], A, B23);
            }
            {
                ull B01 = pk2(b3.x, b3.y), B23 = pk2(b3.z, b3.w);
                ull A;
                A = pk2(a0.w, a0.w); fma2(acc[0][0], A, B01); fma2(acc[0][1], A, B23);
                A = pk2(a1.w, a1.w); fma2(acc[1][0], A, B01); fma2(acc[1][1], A, B23);
                A = pk2(a2.w, a2.w); fma2(acc[2][0], A, B01); fma2(acc[2][1], A, B23);
                A = pk2(a3.w, a3.w); fma2(acc[3][0], A, B01); fma2(acc[3][1], A, B23);
            }
        }
        __syncthreads();
    }

    float4 bias = *(const float4*)&preB[tx * 4];
#pragma unroll
    for (int i = 0; i < 4; i++) {
        int p = e0 + ty * 4 + i;
        if (p >= E_) continue;
        float x0, x1, x2, x3;
        upk2(acc[i][0], x0, x1);
        upk2(acc[i][1], x2, x3);
        float4 o = make_float4(x0 + bias.x, x1 + bias.y, x2 + bias.z, x3 + bias.w);
        *(float4*)(g_m + (size_t)p * 64 + tx * 4) = o;
    }
}

/* ------------------------------------------------------------------ */
/* Aggregate: warp per node, CSR walk, 4-wide unrolled for MLP         */
/* ------------------------------------------------------------------ */
__global__ void k_agg()
{
    int gw   = (blockIdx.x * blockDim.x + threadIdx.x) >> 5;
    int lane = threadIdx.x & 31;
    if (gw >= N_) return;

    int r0 = g_rowoff[gw], r1 = g_rowoff[gw + 1];
    float sx = 0.f, sy = 0.f, qx = 0.f, qy = 0.f;
    float mxx = -INFINITY, mxy = -INFINITY;
    float mnx =  INFINITY, mny =  INFINITY;

    const float2* M = (const float2*)g_m;
    int p = r0;
    for (; p + 4 <= r1; p += 4) {
        float2 v0 = M[(p + 0) * 32 + lane];
        float2 v1 = M[(p + 1) * 32 + lane];
        float2 v2 = M[(p + 2) * 32 + lane];
        float2 v3 = M[(p + 3) * 32 + lane];
        sx += v0.x; sy += v0.y;
        qx = fmaf(v0.x, v0.x, qx); qy = fmaf(v0.y, v0.y, qy);
        mxx = fmaxf(mxx, v0.x); mxy = fmaxf(mxy, v0.y);
        mnx = fminf(mnx, v0.x); mny = fminf(mny, v0.y);
        sx += v1.x; sy += v1.y;
        qx = fmaf(v1.x, v1.x, qx); qy = fmaf(v1.y, v1.y, qy);
        mxx = fmaxf(mxx, v1.x); mxy = fmaxf(mxy, v1.y);
        mnx = fminf(mnx, v1.x); mny = fminf(mny, v1.y);
        sx += v2.x; sy += v2.y;
        qx = fmaf(v2.x, v2.x, qx); qy = fmaf(v2.y, v2.y, qy);
        mxx = fmaxf(mxx, v2.x); mxy = fmaxf(mxy, v2.y);
        mnx = fminf(mnx, v2.x); mny = fminf(mny, v2.y);
        sx += v3.x; sy += v3.y;
        qx = fmaf(v3.x, v3.x, qx); qy = fmaf(v3.y, v3.y, qy);
        mxx = fmaxf(mxx, v3.x); mxy = fmaxf(mxy, v3.y);
        mnx = fminf(mnx, v3.x); mny = fminf(mny, v3.y);
    }
    for (; p < r1; p++) {
        float2 v = M[p * 32 + lane];
        sx += v.x; sy += v.y;
        qx = fmaf(v.x, v.x, qx); qy = fmaf(v.y, v.y, qy);
        mxx = fmaxf(mxx, v.x); mxy = fmaxf(mxy, v.y);
        mnx = fminf(mnx, v.x); mny = fminf(mny, v.y);
    }
    int   deg  = r1 - r0;
    float degc = fmaxf((float)deg, 1.0f);
    float meanx = sx / degc, meany = sy / degc;
    float msqx  = qx / degc, msqy  = qy / degc;
    float stdx = sqrtf(fmaxf(msqx - meanx * meanx, 0.f) + 1e-5f);
    float stdy = sqrtf(fmaxf(msqy - meany * meany, 0.f) + 1e-5f);
    if (deg == 0) { mxx = mxy = 0.f; mnx = mny = 0.f; }

    float2* A = (float2*)(g_agg + gw * (4 * H_));
    A[lane]      = make_float2(meanx, meany);
    A[32 + lane] = make_float2(mxx, mxy);
    A[64 + lane] = make_float2(mnx, mny);
    A[96 + lane] = make_float2(stdx, stdy);
}

/* ------------------------------------------------------------------ */
/* Posttrans GEMM, 3-accumulator reformulation (R12 version, BM=64)    */
/* ------------------------------------------------------------------ */
__global__ void __launch_bounds__(256)
k_post(const float* __restrict__ postW, const float* __restrict__ postB)
{
    __shared__ float sA[32][65];
    __shared__ float sB0[32][68];
    __shared__ float sB1[32][68];
    __shared__ float sB2[32][68];
    __shared__ float sAmp[64], sAtt[64];

    int t  = threadIdx.x;
    int n0 = blockIdx.x * 64;
    if (t < 64) {
        int n = n0 + t;
        sAmp[t] = (n < N_) ? g_amp[n] : 0.f;
        sAtt[t] = (n < N_) ? g_att[n] : 0.f;
    }
    __syncthreads();

    int tx = t & 15, ty = t >> 4;
    ull acc0[4][2], acc1[4][2], acc2[4][2];
#pragma unroll
    for (int i = 0; i < 4; i++) {
        acc0[i][0] = 0ull; acc0[i][1] = 0ull;
        acc1[i][0] = 0ull; acc1[i][1] = 0ull;
        acc2[i][0] = 0ull; acc2[i][1] = 0ull;
    }

    /* main: 8 phases over agg K=256, three weight tiles per phase */
    for (int kt = 0; kt < 8; kt++) {
#pragma unroll
        for (int r = 0; r < 2; r++) {
            int li = t + 256 * r;           /* float4 index 0..511 */
            int kl = li >> 4, c4 = li & 15;
            int row = kt * 32 + kl;
            *(float4*)&sB0[kl][c4 * 4] = *(const float4*)(postW + row * 64 + c4 * 4);
            *(float4*)&sB1[kl][c4 * 4] = *(const float4*)(postW + (256 + row) * 64 + c4 * 4);
            *(float4*)&sB2[kl][c4 * 4] = *(const float4*)(postW + (512 + row) * 64 + c4 * 4);
        }
#pragma unroll
        for (int r = 0; r < 8; r++) {
            int li = t + 256 * r;
            int nl = li >> 5, kl = li & 31;
            int n  = n0 + nl;
            sA[kl][nl] = (n < N_) ? g_agg[n * 256 + kt * 32 + kl] : 0.f;
        }
        __syncthreads();
#pragma unroll 4
        for (int kk = 0; kk < 32; kk++) {
            float a0 = sA[kk][ty * 4 + 0];
            float a1 = sA[kk][ty * 4 + 1];
            float a2 = sA[kk][ty * 4 + 2];
            float a3 = sA[kk][ty * 4 + 3];
            ull A0 = pk2(a0, a0), A1 = pk2(a1, a1);
            ull A2 = pk2(a2, a2), A3 = pk2(a3, a3);
            {
                float4 b = *(const float4*)&sB0[kk][tx * 4];
                ull B01 = pk2(b.x, b.y), B23 = pk2(b.z, b.w);
                fma2(acc0[0][0], A0, B01); fma2(acc0[0][1], A0, B23);
                fma2(acc0[1][0], A1, B01); fma2(acc0[1][1], A1, B23);
                fma2(acc0[2][0], A2, B01); fma2(acc0[2][1], A2, B23);
                fma2(acc0[3][0], A3, B01); fma2(acc0[3][1], A3, B23);
            }
            {
                float4 b = *(const float4*)&sB1[kk][tx * 4];
                ull B01 = pk2(b.x, b.y), B23 = pk2(b.z, b.w);
                fma2(acc1[0][0], A0, B01); fma2(acc1[0][1], A0, B23);
                fma2(acc1[1][0], A1, B01); fma2(acc1[1][1], A1, B23);
                fma2(acc1[2][0], A2, B01); fma2(acc1[2][1], A2, B23);
                fma2(acc1[3][0], A3, B01); fma2(acc1[3][1], A3, B23);
            }
            {
                float4 b = *(const float4*)&sB2[kk][tx * 4];
                ull B01 = pk2(b.x, b.y), B23 = pk2(b.z, b.w);
                fma2(acc2[0][0], A0, B01); fma2(acc2[0][1], A0, B23);
                fma2(acc2[1][0], A1, B01); fma2(acc2[1][1], A1, B23);
                fma2(acc2[2][0], A2, B01); fma2(acc2[2][1], A2, B23);
                fma2(acc2[3][0], A3, B01); fma2(acc2[3][1], A3, B23);
            }
        }
        __syncthreads();
    }

    /* tail: x @ W3 (rows 768..831) accumulated into acc0 */
    for (int kt2 = 0; kt2 < 2; kt2++) {
#pragma unroll
        for (int r = 0; r < 2; r++) {
            int li = t + 256 * r;
            int kl = li >> 4, c4 = li & 15;
            int row = 768 + kt2 * 32 + kl;
            *(float4*)&sB0[kl][c4 * 4] = *(const float4*)(postW + row * 64 + c4 * 4);
        }
#pragma unroll
        for (int r = 0; r < 8; r++) {
            int li = t + 256 * r;
            int nl = li >> 5, kl = li & 31;
            int n  = n0 + nl;
            sA[kl][nl] = (n < N_) ? g_x[n * 64 + kt2 * 32 + kl] : 0.f;
        }
        __syncthreads();
#pragma unroll 8
        for (int kk = 0; kk < 32; kk++) {
            float4 b = *(const float4*)&sB0[kk][tx * 4];
            ull B01 = pk2(b.x, b.y), B23 = pk2(b.z, b.w);
#pragma unroll
            for (int i = 0; i < 4; i++) {
                float a = sA[kk][ty * 4 + i];
                ull A = pk2(a, a);
                fma2(acc0[i][0], A, B01);
                fma2(acc0[i][1], A, B23);
            }
        }
        __syncthreads();
    }

    /* epilogue: y = acc0 + amp*acc1 + att*acc2 + bias */
#pragma unroll
    for (int i = 0; i < 4; i++) {
        int n = n0 + ty * 4 + i;
        if (n >= N_) continue;
        float amp = sAmp[ty * 4 + i];
        float att = sAtt[ty * 4 + i];
        float y[4], u1[4], u2[4];
        upk2(acc0[i][0], y[0], y[1]);
        upk2(acc0[i][1], y[2], y[3]);
        upk2(acc1[i][0], u1[0], u1[1]);
        upk2(acc1[i][1], u1[2], u1[3]);
        upk2(acc2[i][0], u2[0], u2[1]);
        upk2(acc2[i][1], u2[2], u2[3]);
        int c = tx * 4;
#pragma unroll
        for (int j = 0; j < 4; j++) {
            float v = y[j] + amp * u1[j] + att * u2[j] + postB[c + j];
            g_y[n * 64 + c + j] = v;
        }
    }
}

/* ------------------------------------------------------------------ */
/* Mix (R14 version)                                                   */
/* ------------------------------------------------------------------ */
__global__ void __launch_bounds__(256, 4)
k_mix(const float* __restrict__ mixW,
      const float* __restrict__ mixB,
      const float* __restrict__ snorm)
{
    __shared__ float sY[64][68];   /* [node][k], natural layout */
    __shared__ float sW[64][68];   /* [k][col]                  */

    int t  = threadIdx.x;
    int n0 = blockIdx.x * 64;
    int tx = t & 15, ty = t >> 4;

#pragma unroll
    for (int r = 0; r < 4; r++) {
        int li  = t + 256 * r;
        int row = li >> 4, c4 = li & 15;
        int n = n0 + row;
        float4 yv = make_float4(0.f, 0.f, 0.f, 0.f);
        if (n < N_) yv = *(const float4*)(g_y + n * 64 + c4 * 4);
        *(float4*)&sY[row][c4 * 4] = yv;
        *(float4*)&sW[row][c4 * 4] = *(const float4*)(mixW + row * 64 + c4 * 4);
    }
    __syncthreads();

    ull acc[4][2];
#pragma unroll
    for (int i = 0; i < 4; i++) { acc[i][0] = pk2(0.f, 0.f); acc[i][1] = pk2(0.f, 0.f); }

#pragma unroll 4
    for (int k4 = 0; k4 < 16; k4++) {
        float4 a0 = *(const float4*)&sY[ty * 4 + 0][k4 * 4];
        float4 a1 = *(const float4*)&sY[ty * 4 + 1][k4 * 4];
        float4 a2 = *(const float4*)&sY[ty * 4 + 2][k4 * 4];
        float4 a3 = *(const float4*)&sY[ty * 4 + 3][k4 * 4];
        float4 b0 = *(const float4*)&sW[k4 * 4 + 0][tx * 4];
        float4 b1 = *(const float4*)&sW[k4 * 4 + 1][tx * 4];
        float4 b2 = *(const float4*)&sW[k4 * 4 + 2][tx * 4];
        float4 b3 = *(const float4*)&sW[k4 * 4 + 3][tx * 4];

        {
            ull B01 = pk2(b0.x, b0.y), B23 = pk2(b0.z, b0.w);
            ull A;
            A = pk2(a0.x, a0.x); fma2(acc[0][0], A, B01); fma2(acc[0][1], A, B23);
            A = pk2(a1.x, a1.x); fma2(acc[1][0], A, B01); fma2(acc[1][1], A, B23);
            A = pk2(a2.x, a2.x); fma2(acc[2][0], A, B01); fma2(acc[2][1], A, B23);
            A = pk2(a3.x, a3.x); fma2(acc[3][0], A, B01); fma2(acc[3][1], A, B23);
        }
        {
            ull B01 = pk2(b1.x, b1.y), B23 = pk2(b1.z, b1.w);
            ull A;
            A = pk2(a0.y, a0.y); fma2(acc[0][0], A, B01); fma2(acc[0][1], A, B23);
            A = pk2(a1.y, a1.y); fma2(acc[1][0], A, B01); fma2(acc[1][1], A, B23);
            A = pk2(a2.y, a2.y); fma2(acc[2][0], A, B01); fma2(acc[2][1], A, B23);
            A = pk2(a3.y, a3.y); fma2(acc[3][0], A, B01); fma2(acc[3][1], A, B23);
        }
        {
            ull B01 = pk2(b2.x, b2.y), B23 = pk2(b2.z, b2.w);
            ull A;
            A = pk2(a0.z, a0.z); fma2(acc[0][0], A, B01); fma2(acc[0][1], A, B23);
            A = pk2(a1.z, a1.z); fma2(acc[1][0], A, B01); fma2(acc[1][1], A, B23);
            A = pk2(a2.z, a2.z); fma2(acc[2][0], A, B01); fma2(acc[2][1], A, B23);
            A = pk2(a3.z, a3.z); fma2(acc[3][0], A, B01); fma2(acc[3][1], A, B23);
        }
        {
            ull B01 = pk2(b3.x, b3.y), B23 = pk2(b3.z, b3.w);
            ull A;
            A = pk2(a0.w, a0.w); fma2(acc[0][0], A, B01); fma2(acc[0][1], A, B23);
            A = pk2(a1.w, a1.w); fma2(acc[1][0], A, B01); fma2(acc[1][1], A, B23);
            A = pk2(a2.w, a2.w); fma2(acc[2][0], A, B01); fma2(acc[2][1], A, B23);
            A = pk2(a3.w, a3.w); fma2(acc[3][0], A, B01); fma2(acc[3][1], A, B23);
        }
    }

#pragma unroll
    for (int i = 0; i < 4; i++) {
        int n = n0 + ty * 4 + i;
        if (n >= N_) continue;
        float sn = snorm[n];
        float v[4];
        upk2(acc[i][0], v[0], v[1]);
        upk2(acc[i][1], v[2], v[3]);
        float* xp = g_x + n * 64 + tx * 4;
        float4 cur = *(float4*)xp;
        float u0 = v[0] + mixB[tx * 4 + 0]; u0 = (u0 > 0.f) ? u0 : 0.01f * u0;
        float u1 = v[1] + mixB[tx * 4 + 1]; u1 = (u1 > 0.f) ? u1 : 0.01f * u1;
        float u2 = v[2] + mixB[tx * 4 + 2]; u2 = (u2 > 0.f) ? u2 : 0.01f * u2;
        float u3 = v[3] + mixB[tx * 4 + 3]; u3 = (u3 > 0.f) ? u3 : 0.01f * u3;
        cur.x += u0 * sn; cur.y += u1 * sn;
        cur.z += u2 * sn; cur.w += u3 * sn;
        *(float4*)xp = cur;
    }
}

/* ------------------------------------------------------------------ */
/* Readout                                                             */
/* ------------------------------------------------------------------ */
__global__ void k_gaccum(const int* __restrict__ gid)
{
    int id = blockIdx.x * blockDim.x + threadIdx.x;
    if (id >= N_ * H_) return;
    int n = id >> 6, c = id & 63;
    atomicAdd(&g_gsum[gid[n] * 64 + c], g_x[id]);
}

__global__ void k_final(const float* __restrict__ r1W, const float* __restrict__ r1B,
                        const float* __restrict__ r2W, const float* __restrict__ r2B,
                        const float* __restrict__ r3W, const float* __restrict__ r3B,
                        float* __restrict__ out)
{
    int g = threadIdx.x;
    if (g >= G_) return;
    float cnt = fmaxf(g_gcnt[g], 1.0f);
    float hg[64];
#pragma unroll
    for (int k = 0; k < 64; k++) hg[k] = g_gsum[g * 64 + k] / cnt;

    float t1[32];
#pragma unroll
    for (int j = 0; j < 32; j++) {
        float a = r1B[j];
        for (int k = 0; k < 64; k++) a = fmaf(hg[k], r1W[k * 32 + j], a);
        t1[j] = fmaxf(a, 0.f);
    }
    float t2[16];
#pragma unroll
    for (int j = 0; j < 16; j++) {
        float a = r2B[j];
        for (int k = 0; k < 32; k++) a = fmaf(t1[k], r2W[k * 16 + j], a);
        t2[j] = fmaxf(a, 0.f);
    }
#pragma unroll
    for (int c = 0; c < 10; c++) {
        float a = r3B[c];
        for (int k = 0; k < 16; k++) a = fmaf(t2[k], r3W[k * 10 + c], a);
        out[g * 10 + c] = a;
    }
}

/* trailing re-zero so the next replay starts from clean counters      */
__global__ void k_rezero()
{
    int i = blockIdx.x * blockDim.x + threadIdx.x;
    if (i < N_)       g_degi[i] = 0;
    if (i < G_)       g_gcnt[i] = 0.f;
    if (i < G_ * H_)  g_gsum[i] = 0.f;
}

/* ------------------------------------------------------------------ */
/* Host launch                                                         */
/* ------------------------------------------------------------------ */
extern "C" void kernel_launch(void* const* d_in, const int* in_sizes, int n_in,
                              void* d_out, int out_size)
{
    const float* h      = (const float*)d_in[0];
    const float* snorm  = (const float*)d_in[1];
    const float* embW   = (const float*)d_in[2];
    const float* embB   = (const float*)d_in[3];
    const float* preW   = (const float*)d_in[4];
    const float* preB   = (const float*)d_in[5];
    const float* postW  = (const float*)d_in[6];
    const float* postB  = (const float*)d_in[7];
    const float* mixW   = (const float*)d_in[8];
    const float* mixB   = (const float*)d_in[9];
    const float* r1W    = (const float*)d_in[10];
    const float* r1B    = (const float*)d_in[11];
    const float* r2W    = (const float*)d_in[12];
    const float* r2B    = (const float*)d_in[13];
    const float* r3W    = (const float*)d_in[14];
    const float* r3B    = (const float*)d_in[15];
    const int*   src    = (const int*)d_in[16];
    const int*   dst    = (const int*)d_in[17];
    const int*   gid    = (const int*)d_in[18];
    float* out = (float*)d_out;

    /* 3 prelude launches; k_edge layer-0 is launch #4 = ncu slot */
    k_count_gcnt          <<<(E_ + 255) / 256, 256>>>(dst, gid);
    k_scan                <<<1, 1024>>>();
    k_scatter_scalers_embed<<<(N_ * H_ + 255) / 256, 256>>>(src, dst, h, embW, embB);

    for (int i = 0; i < L_; i++) {
        k_edge<<<(E_ + 63) / 64, 256>>>(preW + i * 128 * 64, preB + i * 64);
        k_agg <<<(N_ * 32 + 255) / 256, 256>>>();
        k_post<<<(N_ + 63) / 64, 256>>>(postW + i * 832 * 64, postB + i * 64);
        k_mix <<<(N_ + 63) / 64, 256>>>(mixW + i * 64 * 64, mixB + i * 64, snorm);
    }

    k_gaccum<<<(N_ * H_ + 255) / 256, 256>>>(gid);
    k_final <<<1, 128>>>(r1W, r1B, r2W, r2B, r3W, r3B, out);
    k_rezero<<<(N_ + 255) / 256, 256>>>();
}